// round 6
// baseline (speedup 1.0000x reference)
#include <cuda_runtime.h>
#include <cuda_bf16.h>

#define LOOP 100
#define BN_EPS 1e-5f

__device__ __forceinline__ float ex2_approx(float x) {
    float y; asm("ex2.approx.f32 %0, %1;" : "=f"(y) : "f"(x)); return y;
}
__device__ __forceinline__ float rcp_approx(float x) {
    float y; asm("rcp.approx.f32 %0, %1;" : "=f"(y) : "f"(x)); return y;
}
__device__ __forceinline__ float tanh_approx(float x) {
    float y; asm("tanh.approx.f32 %0, %1;" : "=f"(y) : "f"(x)); return y;
}
__device__ __forceinline__ float sqrt_approx(float x) {
    float y; asm("sqrt.approx.f32 %0, %1;" : "=f"(y) : "f"(x)); return y;
}
__device__ __forceinline__ float fast_sigmoid(float a) {
    return rcp_approx(1.0f + ex2_approx(-a * 1.4426950408889634f));
}

__global__ void __launch_bounds__(256, 1)
model_fused_kernel(const float* __restrict__ x,
                   const float* __restrict__ conv_w,
                   const float* __restrict__ conv_b,
                   const float* __restrict__ bn_gamma,
                   const float* __restrict__ bn_beta,
                   const float* __restrict__ bn_mean,
                   const float* __restrict__ bn_var,
                   const float* __restrict__ w1,
                   const float* __restrict__ b1,
                   const float* __restrict__ w2,
                   const float* __restrict__ b2,
                   const float* __restrict__ w3,
                   const float* __restrict__ b3,
                   float* __restrict__ out)
{
    // kk: flat history kk[t*16+p]; feats[i][j] = kk[i*100+j]
    __shared__ __align__(16) float kk[LOOP * 16];
    __shared__ __align__(16) float w1s[60 * 100];
    __shared__ __align__(16) float w2s[16 * 60];
    __shared__ __align__(16) float w3s[8 * 16];
    __shared__ __align__(16) float h1n[16 * 60];
    __shared__ __align__(16) float h2s[16 * 16];
    __shared__ float b1s[60];
    __shared__ float b2s[16];
    __shared__ float b3s[8];

    const int tid = threadIdx.x;

    if (tid < 32) {
        // ======== Phase 1: serial conv recurrence — FULL warp 0 ==============
        // Lanes 16-31 compute harmless duplicates (no divergence inside the
        // loop, so bar.arrive is warp-uniform). Only lanes 0-15 store.
        const int p16 = tid & 15;
        const int r = p16 >> 2;
        const int c = p16 & 3;

        // Halved, boundary-masked weights -> recurrence computes a' = a/2
        float wm[9];
        int   ln[9];
        #pragma unroll
        for (int dr = 0; dr < 3; dr++) {
            #pragma unroll
            for (int dc = 0; dc < 3; dc++) {
                const int nr = r + dr - 1;
                const int nc = c + dc - 1;
                const bool ok = ((unsigned)nr < 4u) && ((unsigned)nc < 4u);
                const int k = dr * 3 + dc;
                wm[k] = ok ? 0.5f * conv_w[k] : 0.0f;
                ln[k] = ok ? (nr * 4 + nc) : p16;
            }
        }
        const float cbh     = 0.5f * conv_b[0];
        const float inv_std = bn_gamma[0] * rsqrtf(bn_var[0] + BN_EPS);
        const float shift   = bn_beta[0] - bn_mean[0] * inv_std;
        const float c1      = 2.0f * inv_std;   // 0.5*inv_std*a^2 = 2*inv_std*a'^2
        const float sh2     = 2.0f * shift;     // a*shift = 2*shift*a'

        float v = x[p16];

        #pragma unroll 5
        for (int t = 0; t < LOOP; t++) {
            // 8 neighbor shuffles (full-warp, full mask); center term overlaps
            const float n0 = __shfl_sync(0xFFFFFFFFu, v, ln[0]);
            const float n1 = __shfl_sync(0xFFFFFFFFu, v, ln[1]);
            const float n2 = __shfl_sync(0xFFFFFFFFu, v, ln[2]);
            const float n3 = __shfl_sync(0xFFFFFFFFu, v, ln[3]);
            const float n5 = __shfl_sync(0xFFFFFFFFu, v, ln[5]);
            const float n6 = __shfl_sync(0xFFFFFFFFu, v, ln[6]);
            const float n7 = __shfl_sync(0xFFFFFFFFu, v, ln[7]);
            const float n8 = __shfl_sync(0xFFFFFFFFu, v, ln[8]);

            const float q  = fmaf(wm[4], v, cbh);
            float p0 = fmaf(wm[0], n0, q);
            p0       = fmaf(wm[7], n7, p0);
            const float p1 = fmaf(wm[2], n2, wm[1] * n1);
            const float p2 = fmaf(wm[5], n5, wm[3] * n3);
            const float p3 = fmaf(wm[8], n8, wm[6] * n6);
            const float ap = (p0 + p1) + (p2 + p3);   // a' = a/2

            // h = p*tanh(a') + (p + 2*shift*a'),  p = 2*inv_std*a'^2
            const float th = tanh_approx(ap);
            const float t1 = ap * c1;
            const float p  = ap * t1;
            const float pq = fmaf(ap, sh2, p);
            const float h  = fmaf(p, th, pq);

            // xn = sign(h)*sqrt(|h|); fabs folds into the MUFU operand
            const float xn = copysignf(sqrt_approx(fabsf(h)), h);

            if (tid < 16) kk[t * 16 + tid] = xn;   // predicated store
            v = xn;

            // Publish chunk boundaries: rows 4c..4c+3 ready after t=25c+24.
            // bar.arrive is non-blocking; consumers sleep in bar.sync.
            if (t == 24) { __threadfence_block(); asm volatile("bar.arrive 2, 256;" ::: "memory"); }
            if (t == 49) { __threadfence_block(); asm volatile("bar.arrive 3, 256;" ::: "memory"); }
            if (t == 74) { __threadfence_block(); asm volatile("bar.arrive 4, 256;" ::: "memory"); }
        }
    } else {
        // ======== Warps 1-7: prefetch weights, then consume kk chunks ========
        const int pt = tid - 32;             // 0..223
        const int NP = 224;
        for (int i = pt; i < 6000; i += NP) w1s[i] = w1[i];
        for (int i = pt; i < 960;  i += NP) w2s[i] = w2[i];
        for (int i = pt; i < 128;  i += NP) w3s[i] = w3[i];
        for (int i = pt; i < 60;   i += NP) b1s[i] = b1[i];
        if (pt < 16) b2s[pt] = b2[pt];
        if (pt < 8)  b3s[pt] = b3[pt];

        // order consumer prefetches before any consumer reads w1s
        asm volatile("bar.sync 1, 224;" ::: "memory");

        // chunks 0..2 overlapped with phase 1; bar.sync = HW sleep (no issue
        // slots stolen from warp 0 while waiting)
        #pragma unroll
        for (int cchunk = 0; cchunk < 3; cchunk++) {
            if (cchunk == 0) asm volatile("bar.sync 2, 256;" ::: "memory");
            if (cchunk == 1) asm volatile("bar.sync 3, 256;" ::: "memory");
            if (cchunk == 2) asm volatile("bar.sync 4, 256;" ::: "memory");
            for (int task = pt; task < 240; task += NP) {
                const int i = cchunk * 4 + task / 60;
                const int o = task % 60;
                const float4* f4 = (const float4*)&kk[i * 100];
                const float4* g4 = (const float4*)&w1s[o * 100];
                float a0 = 0.f, a1 = 0.f, a2 = 0.f, a3 = 0.f;
                #pragma unroll
                for (int j = 0; j < 25; j++) {
                    const float4 f = f4[j];
                    const float4 g = g4[j];
                    a0 = fmaf(f.x, g.x, a0);
                    a1 = fmaf(f.y, g.y, a1);
                    a2 = fmaf(f.z, g.z, a2);
                    a3 = fmaf(f.w, g.w, a3);
                }
                const float hv = (a0 + a1) + (a2 + a3) + b1s[o];
                const float sw = hv * fast_sigmoid(hv);
                h1n[i * 60 + o] = 2.0f * sw - 1.0f;
            }
        }
    }
    __syncthreads();

    // ======== Chunk 3 of phase 2 (rows 12-15), all 256 threads =============
    if (tid < 240) {
        const int i = 12 + tid / 60;
        const int o = tid % 60;
        const float4* f4 = (const float4*)&kk[i * 100];
        const float4* g4 = (const float4*)&w1s[o * 100];
        float a0 = 0.f, a1 = 0.f, a2 = 0.f, a3 = 0.f;
        #pragma unroll
        for (int j = 0; j < 25; j++) {
            const float4 f = f4[j];
            const float4 g = g4[j];
            a0 = fmaf(f.x, g.x, a0);
            a1 = fmaf(f.y, g.y, a1);
            a2 = fmaf(f.z, g.z, a2);
            a3 = fmaf(f.w, g.w, a3);
        }
        const float hv = (a0 + a1) + (a2 + a3) + b1s[o];
        const float sw = hv * fast_sigmoid(hv);
        h1n[i * 60 + o] = 2.0f * sw - 1.0f;
    }
    __syncthreads();

    const int warp = tid >> 5;
    const int lane = tid & 31;
    const int i    = lane & 15;
    const int sub  = lane >> 4;

    // ======== Phase 3: h2 = swish(h1n @ w2.T + b2), 16x16 ==================
    {
        const int o = 2 * warp + sub;                // 0..15
        const float4* f4 = (const float4*)&h1n[i * 60];
        const float4* g4 = (const float4*)&w2s[o * 60];
        float a0 = 0.f, a1 = 0.f, a2 = 0.f, a3 = 0.f;
        #pragma unroll
        for (int j = 0; j < 15; j++) {
            const float4 f = f4[j];
            const float4 g = g4[j];
            a0 = fmaf(f.x, g.x, a0);
            a1 = fmaf(f.y, g.y, a1);
            a2 = fmaf(f.z, g.z, a2);
            a3 = fmaf(f.w, g.w, a3);
        }
        const float hv = (a0 + a1) + (a2 + a3) + b2s[o];
        h2s[i * 16 + o] = hv * fast_sigmoid(hv);
    }
    __syncthreads();

    // ======== Phase 4: y = h2 @ w3.T + b3 (128 outputs) ====================
    if (tid < 128) {
        const int ii = tid >> 3;
        const int o  = tid & 7;
        const float4* f4 = (const float4*)&h2s[ii * 16];
        const float4* g4 = (const float4*)&w3s[o * 16];
        float acc = 0.f;
        #pragma unroll
        for (int j = 0; j < 4; j++) {
            const float4 f = f4[j];
            const float4 g = g4[j];
            acc = fmaf(f.x, g.x, acc);
            acc = fmaf(f.y, g.y, acc);
            acc = fmaf(f.z, g.z, acc);
            acc = fmaf(f.w, g.w, acc);
        }
        out[tid] = acc + b3s[o];
    }
}

extern "C" void kernel_launch(void* const* d_in, const int* in_sizes, int n_in,
                              void* d_out, int out_size)
{
    const float* x        = (const float*)d_in[0];
    const float* conv_w   = (const float*)d_in[1];
    const float* conv_b   = (const float*)d_in[2];
    const float* bn_gamma = (const float*)d_in[3];
    const float* bn_beta  = (const float*)d_in[4];
    const float* bn_mean  = (const float*)d_in[5];
    const float* bn_var   = (const float*)d_in[6];
    const float* w1       = (const float*)d_in[7];
    const float* b1       = (const float*)d_in[8];
    const float* w2       = (const float*)d_in[9];
    const float* b2       = (const float*)d_in[10];
    const float* w3       = (const float*)d_in[11];
    const float* b3       = (const float*)d_in[12];
    float* out = (float*)d_out;

    model_fused_kernel<<<1, 256>>>(x, conv_w, conv_b, bn_gamma, bn_beta,
                                   bn_mean, bn_var, w1, b1, w2, b2, w3, b3, out);
}

// round 7
// speedup vs baseline: 1.1379x; 1.1379x over previous
#include <cuda_runtime.h>
#include <cuda_bf16.h>

#define LOOP 100
#define BN_EPS 1e-5f

__device__ __forceinline__ float ex2_approx(float x) {
    float y; asm("ex2.approx.f32 %0, %1;" : "=f"(y) : "f"(x)); return y;
}
__device__ __forceinline__ float rcp_approx(float x) {
    float y; asm("rcp.approx.f32 %0, %1;" : "=f"(y) : "f"(x)); return y;
}
__device__ __forceinline__ float tanh_approx(float x) {
    float y; asm("tanh.approx.f32 %0, %1;" : "=f"(y) : "f"(x)); return y;
}
__device__ __forceinline__ float sqrt_approx(float x) {
    float y; asm("sqrt.approx.f32 %0, %1;" : "=f"(y) : "f"(x)); return y;
}
__device__ __forceinline__ float fast_sigmoid(float a) {
    return rcp_approx(1.0f + ex2_approx(-a * 1.4426950408889634f));
}

__global__ void __launch_bounds__(256, 1)
model_fused_kernel(const float* __restrict__ x,
                   const float* __restrict__ conv_w,
                   const float* __restrict__ conv_b,
                   const float* __restrict__ bn_gamma,
                   const float* __restrict__ bn_beta,
                   const float* __restrict__ bn_mean,
                   const float* __restrict__ bn_var,
                   const float* __restrict__ w1,
                   const float* __restrict__ b1,
                   const float* __restrict__ w2,
                   const float* __restrict__ b2,
                   const float* __restrict__ w3,
                   const float* __restrict__ b3,
                   float* __restrict__ out)
{
    // kk: flat history kk[t*16+p]; feats[i][j] = kk[i*100+j]
    __shared__ __align__(16) float kk[LOOP * 16];
    __shared__ __align__(16) float w1s[60 * 100];
    __shared__ __align__(16) float w2s[16 * 60];
    __shared__ __align__(16) float w3s[8 * 16];
    __shared__ __align__(16) float h1n[16 * 60];
    __shared__ __align__(16) float h2s[16 * 16];
    __shared__ float b1s[60];
    __shared__ float b2s[16];
    __shared__ float b3s[8];

    const int tid = threadIdx.x;

    if (tid >= 224) {
        // ======== Phase 1: serial conv recurrence — WARP 7 (highest wid) =====
        // Hi-wid-first arbiter: the producer wins every issue-slot tie against
        // the prefetching consumer warps. Lanes 16-31 compute duplicates; only
        // lanes 0-15 store (predicated, no divergence).
        const int lane = tid & 31;
        const int p16  = lane & 15;
        const int r = p16 >> 2;
        const int c = p16 & 3;

        // Halved, boundary-masked weights -> recurrence computes a' = a/2
        float wm[9];
        int   ln[9];
        #pragma unroll
        for (int dr = 0; dr < 3; dr++) {
            #pragma unroll
            for (int dc = 0; dc < 3; dc++) {
                const int nr = r + dr - 1;
                const int nc = c + dc - 1;
                const bool ok = ((unsigned)nr < 4u) && ((unsigned)nc < 4u);
                const int k = dr * 3 + dc;
                wm[k] = ok ? 0.5f * conv_w[k] : 0.0f;
                ln[k] = ok ? (nr * 4 + nc) : p16;
            }
        }
        const float cbh     = 0.5f * conv_b[0];
        const float inv_std = bn_gamma[0] * rsqrtf(bn_var[0] + BN_EPS);
        const float shift   = bn_beta[0] - bn_mean[0] * inv_std;
        const float c1      = 2.0f * inv_std;   // 0.5*inv_std*a^2 = 2*inv_std*a'^2
        const float sh2     = 2.0f * shift;     // a*shift = 2*shift*a'

        float v = x[p16];

        #pragma unroll 5
        for (int t = 0; t < LOOP; t++) {
            // 8 neighbor shuffles; center term q overlaps the shfl latency
            const float n0 = __shfl_sync(0xFFFFFFFFu, v, ln[0]);
            const float n1 = __shfl_sync(0xFFFFFFFFu, v, ln[1]);
            const float n2 = __shfl_sync(0xFFFFFFFFu, v, ln[2]);
            const float n3 = __shfl_sync(0xFFFFFFFFu, v, ln[3]);
            const float n5 = __shfl_sync(0xFFFFFFFFu, v, ln[5]);
            const float n6 = __shfl_sync(0xFFFFFFFFu, v, ln[6]);
            const float n7 = __shfl_sync(0xFFFFFFFFu, v, ln[7]);
            const float n8 = __shfl_sync(0xFFFFFFFFu, v, ln[8]);

            const float q  = fmaf(wm[4], v, cbh);
            float p0 = fmaf(wm[0], n0, q);
            p0       = fmaf(wm[7], n7, p0);
            const float p1 = fmaf(wm[2], n2, wm[1] * n1);
            const float p2 = fmaf(wm[5], n5, wm[3] * n3);
            const float p3 = fmaf(wm[8], n8, wm[6] * n6);
            const float ap = (p0 + p1) + (p2 + p3);   // a' = a/2

            // h = p*tanh(a') + (p + 2*shift*a'),  p = 2*inv_std*a'^2
            const float th = tanh_approx(ap);
            const float t1 = ap * c1;
            const float p  = ap * t1;
            const float pq = fmaf(ap, sh2, p);
            const float h  = fmaf(p, th, pq);

            // xn = sign(h)*sqrt(|h|); fabs folds into the MUFU operand
            const float xn = copysignf(sqrt_approx(fabsf(h)), h);

            if (lane < 16) kk[t * 16 + p16] = xn;   // predicated store
            v = xn;
        }
    } else {
        // ======== Warps 0-6: prefetch weights, then sleep at __syncthreads ===
        const int pt = tid;                  // 0..223
        const int NP = 224;
        for (int i = pt; i < 6000; i += NP) w1s[i] = w1[i];
        for (int i = pt; i < 960;  i += NP) w2s[i] = w2[i];
        for (int i = pt; i < 128;  i += NP) w3s[i] = w3[i];
        for (int i = pt; i < 60;   i += NP) b1s[i] = b1[i];
        if (pt < 16) b2s[pt] = b2[pt];
        if (pt < 8)  b3s[pt] = b3[pt];
    }
    __syncthreads();   // drains all STS; kk + weights visible to everyone

    const int warp = tid >> 5;
    const int lane = tid & 31;
    const int i    = lane & 15;          // batch row 0..15
    const int sub  = lane >> 4;          // output-column select within warp

    // ======== Phase 2: h1 = 2*swish(feats @ w1.T + b1) - 1 =================
    // Half-warp scheme: weight float4 is half-warp-uniform (broadcast),
    // feature reads at stride 100 are bank-conflict-free.
    #pragma unroll
    for (int pass = 0; pass < 4; pass++) {
        const int o = 2 * (warp + 8 * pass) + sub;   // 0..63
        if (o < 60) {
            const float4* f4 = (const float4*)&kk[i * 100];
            const float4* g4 = (const float4*)&w1s[o * 100];
            float a0 = 0.f, a1 = 0.f, a2 = 0.f, a3 = 0.f;
            #pragma unroll
            for (int j = 0; j < 25; j++) {
                const float4 f = f4[j];
                const float4 g = g4[j];
                a0 = fmaf(f.x, g.x, a0);
                a1 = fmaf(f.y, g.y, a1);
                a2 = fmaf(f.z, g.z, a2);
                a3 = fmaf(f.w, g.w, a3);
            }
            const float hv = (a0 + a1) + (a2 + a3) + b1s[o];
            const float sw = hv * fast_sigmoid(hv);
            h1n[i * 60 + o] = 2.0f * sw - 1.0f;
        }
    }
    __syncthreads();

    // ======== Phase 3: h2 = swish(h1n @ w2.T + b2), 16x16 ==================
    {
        const int o = 2 * warp + sub;                // 0..15
        const float4* f4 = (const float4*)&h1n[i * 60];
        const float4* g4 = (const float4*)&w2s[o * 60];
        float a0 = 0.f, a1 = 0.f, a2 = 0.f, a3 = 0.f;
        #pragma unroll
        for (int j = 0; j < 15; j++) {
            const float4 f = f4[j];
            const float4 g = g4[j];
            a0 = fmaf(f.x, g.x, a0);
            a1 = fmaf(f.y, g.y, a1);
            a2 = fmaf(f.z, g.z, a2);
            a3 = fmaf(f.w, g.w, a3);
        }
        const float hv = (a0 + a1) + (a2 + a3) + b2s[o];
        h2s[i * 16 + o] = hv * fast_sigmoid(hv);
    }
    __syncthreads();

    // ======== Phase 4: y = h2 @ w3.T + b3 (128 outputs) ====================
    if (tid < 128) {
        const int ii = tid >> 3;
        const int o  = tid & 7;
        const float4* f4 = (const float4*)&h2s[ii * 16];
        const float4* g4 = (const float4*)&w3s[o * 16];
        float acc = 0.f;
        #pragma unroll
        for (int j = 0; j < 4; j++) {
            const float4 f = f4[j];
            const float4 g = g4[j];
            acc = fmaf(f.x, g.x, acc);
            acc = fmaf(f.y, g.y, acc);
            acc = fmaf(f.z, g.z, acc);
            acc = fmaf(f.w, g.w, acc);
        }
        out[tid] = acc + b3s[o];
    }
}

extern "C" void kernel_launch(void* const* d_in, const int* in_sizes, int n_in,
                              void* d_out, int out_size)
{
    const float* x        = (const float*)d_in[0];
    const float* conv_w   = (const float*)d_in[1];
    const float* conv_b   = (const float*)d_in[2];
    const float* bn_gamma = (const float*)d_in[3];
    const float* bn_beta  = (const float*)d_in[4];
    const float* bn_mean  = (const float*)d_in[5];
    const float* bn_var   = (const float*)d_in[6];
    const float* w1       = (const float*)d_in[7];
    const float* b1       = (const float*)d_in[8];
    const float* w2       = (const float*)d_in[9];
    const float* b2       = (const float*)d_in[10];
    const float* w3       = (const float*)d_in[11];
    const float* b3       = (const float*)d_in[12];
    float* out = (float*)d_out;

    model_fused_kernel<<<1, 256>>>(x, conv_w, conv_b, bn_gamma, bn_beta,
                                   bn_mean, bn_var, w1, b1, w2, b2, w3, b3, out);
}

// round 9
// speedup vs baseline: 1.1404x; 1.0022x over previous
#include <cuda_runtime.h>
#include <cuda_bf16.h>

#define LOOP 100
#define BN_EPS 1e-5f

__device__ __forceinline__ float ex2_approx(float x) {
    float y; asm("ex2.approx.f32 %0, %1;" : "=f"(y) : "f"(x)); return y;
}
__device__ __forceinline__ float rcp_approx(float x) {
    float y; asm("rcp.approx.f32 %0, %1;" : "=f"(y) : "f"(x)); return y;
}
__device__ __forceinline__ float tanh_approx(float x) {
    float y; asm("tanh.approx.f32 %0, %1;" : "=f"(y) : "f"(x)); return y;
}
__device__ __forceinline__ float sqrt_approx(float x) {
    float y; asm("sqrt.approx.f32 %0, %1;" : "=f"(y) : "f"(x)); return y;
}
__device__ __forceinline__ float fast_sigmoid(float a) {
    return rcp_approx(1.0f + ex2_approx(-a * 1.4426950408889634f));
}

__global__ void __launch_bounds__(256, 1)
model_fused_kernel(const float* __restrict__ x,
                   const float* __restrict__ conv_w,
                   const float* __restrict__ conv_b,
                   const float* __restrict__ bn_gamma,
                   const float* __restrict__ bn_beta,
                   const float* __restrict__ bn_mean,
                   const float* __restrict__ bn_var,
                   const float* __restrict__ w1,
                   const float* __restrict__ b1,
                   const float* __restrict__ w2,
                   const float* __restrict__ b2,
                   const float* __restrict__ w3,
                   const float* __restrict__ b3,
                   float* __restrict__ out)
{
    // kk: flat history kk[t*16+p]; feats[i][j] = kk[i*100+j]
    __shared__ __align__(16) float kk[LOOP * 16];
    __shared__ __align__(16) float w1s[60 * 100];
    __shared__ __align__(16) float w2s[16 * 60];
    __shared__ __align__(16) float w3s[8 * 16];
    __shared__ __align__(16) float h1n[16 * 60];
    __shared__ __align__(16) float h2s[16 * 16];
    __shared__ float b1s[60];
    __shared__ float b2s[16];
    __shared__ float b3s[8];

    const int tid  = threadIdx.x;
    const int wid  = tid >> 5;
    const int lane = tid & 31;

    if (wid == 7) {
        // ======== Phase 1: producer — warp 7 (SMSP 3), full 32 lanes =========
        // Warp 3 (the only other SMSP-3 warp) does NO overlapped compute, so
        // the serial chain owns its scheduler. Lanes 16-31 duplicate; only
        // lanes 0-15 store (predicated, warp-uniform control flow).
        const int p16 = lane & 15;
        const int r = p16 >> 2;
        const int c = p16 & 3;

        float wm[9];
        int   ln[9];
        #pragma unroll
        for (int dr = 0; dr < 3; dr++) {
            #pragma unroll
            for (int dc = 0; dc < 3; dc++) {
                const int nr = r + dr - 1;
                const int nc = c + dc - 1;
                const bool ok = ((unsigned)nr < 4u) && ((unsigned)nc < 4u);
                const int k = dr * 3 + dc;
                wm[k] = ok ? 0.5f * conv_w[k] : 0.0f;   // halved weights
                ln[k] = ok ? (nr * 4 + nc) : p16;
            }
        }
        const float cbh     = 0.5f * conv_b[0];
        const float inv_std = bn_gamma[0] * rsqrtf(bn_var[0] + BN_EPS);
        const float shift   = bn_beta[0] - bn_mean[0] * inv_std;
        const float c1      = 2.0f * inv_std;
        const float sh2     = 2.0f * shift;

        float v = x[p16];

        #pragma unroll
        for (int seg = 0; seg < 4; seg++) {
            #pragma unroll 5
            for (int tt = 0; tt < 25; tt++) {
                const int t = seg * 25 + tt;
                const float n0 = __shfl_sync(0xFFFFFFFFu, v, ln[0]);
                const float n1 = __shfl_sync(0xFFFFFFFFu, v, ln[1]);
                const float n2 = __shfl_sync(0xFFFFFFFFu, v, ln[2]);
                const float n3 = __shfl_sync(0xFFFFFFFFu, v, ln[3]);
                const float n5 = __shfl_sync(0xFFFFFFFFu, v, ln[5]);
                const float n6 = __shfl_sync(0xFFFFFFFFu, v, ln[6]);
                const float n7 = __shfl_sync(0xFFFFFFFFu, v, ln[7]);
                const float n8 = __shfl_sync(0xFFFFFFFFu, v, ln[8]);

                const float q  = fmaf(wm[4], v, cbh);
                float p0 = fmaf(wm[0], n0, q);
                p0       = fmaf(wm[7], n7, p0);
                const float p1 = fmaf(wm[2], n2, wm[1] * n1);
                const float p2 = fmaf(wm[5], n5, wm[3] * n3);
                const float p3 = fmaf(wm[8], n8, wm[6] * n6);
                const float ap = (p0 + p1) + (p2 + p3);   // a' = a/2

                const float th = tanh_approx(ap);
                const float t1 = ap * c1;
                const float p  = ap * t1;
                const float pq = fmaf(ap, sh2, p);
                const float h  = fmaf(p, th, pq);

                const float xn = copysignf(sqrt_approx(fabsf(h)), h);

                if (lane < 16) kk[t * 16 + p16] = xn;
                v = xn;
            }
            // Rows 4*seg..4*seg+3 ready. Publish (off critical chain; arrive is
            // non-blocking). Total participants per barrier: 32 (this warp,
            // arrive) + 192 (consumer warps, sync) = 224 = count.
            if (seg == 0) { __threadfence_block(); asm volatile("bar.arrive 2, 224;" ::: "memory"); }
            if (seg == 1) { __threadfence_block(); asm volatile("bar.arrive 3, 224;" ::: "memory"); }
            if (seg == 2) { __threadfence_block(); asm volatile("bar.arrive 4, 224;" ::: "memory"); }
        }
    } else {
        // ======== Warps 0-6: prefetch weights (224 threads) ===================
        const int pt = tid;                  // 0..223
        const int NP = 224;
        for (int i = pt; i < 6000; i += NP) w1s[i] = w1[i];
        for (int i = pt; i < 960;  i += NP) w2s[i] = w2[i];
        for (int i = pt; i < 128;  i += NP) w3s[i] = w3[i];
        for (int i = pt; i < 60;   i += NP) b1s[i] = b1[i];
        if (pt < 16) b2s[pt] = b2[pt];
        if (pt < 8)  b3s[pt] = b3[pt];

        if (wid != 3) {
            // Computing consumers: warps 0,1,2,4,5,6 (SMSPs 0,1,2 only).
            // Barrier 1 orders ALL prefetch stores (incl. warp 3's) before any
            // consumer w1s read. Participants: 192 sync + 32 arrive = 224.
            asm volatile("bar.sync 1, 224;" ::: "memory");

            const int ct  = (wid < 3) ? wid : wid - 1;     // 0..5
            const int ptc = ct * 32 + lane;                // 0..191

            #pragma unroll
            for (int cchunk = 0; cchunk < 3; cchunk++) {
                if (cchunk == 0) asm volatile("bar.sync 2, 224;" ::: "memory");
                if (cchunk == 1) asm volatile("bar.sync 3, 224;" ::: "memory");
                if (cchunk == 2) asm volatile("bar.sync 4, 224;" ::: "memory");
                for (int task = ptc; task < 240; task += 192) {
                    const int i = cchunk * 4 + task / 60;
                    const int o = task % 60;
                    const float4* f4 = (const float4*)&kk[i * 100];
                    const float4* g4 = (const float4*)&w1s[o * 100];
                    float a0 = 0.f, a1 = 0.f, a2 = 0.f, a3 = 0.f;
                    #pragma unroll
                    for (int j = 0; j < 25; j++) {
                        const float4 f = f4[j];
                        const float4 g = g4[j];
                        a0 = fmaf(f.x, g.x, a0);
                        a1 = fmaf(f.y, g.y, a1);
                        a2 = fmaf(f.z, g.z, a2);
                        a3 = fmaf(f.w, g.w, a3);
                    }
                    const float hv = (a0 + a1) + (a2 + a3) + b1s[o];
                    const float sw = hv * fast_sigmoid(hv);
                    h1n[i * 60 + o] = 2.0f * sw - 1.0f;
                }
            }
        } else {
            // Warp 3 (producer's SMSP partner): publish its prefetch stores to
            // barrier 1 (non-blocking arrive), then sleep at __syncthreads,
            // leaving SMSP 3's issue slots to the producer.
            asm volatile("bar.arrive 1, 224;" ::: "memory");
        }
    }
    __syncthreads();

    // ======== Chunk 3 of phase 2 (rows 12-15), all 256 threads ==============
    if (tid < 240) {
        const int i = 12 + tid / 60;
        const int o = tid % 60;
        const float4* f4 = (const float4*)&kk[i * 100];
        const float4* g4 = (const float4*)&w1s[o * 100];
        float a0 = 0.f, a1 = 0.f, a2 = 0.f, a3 = 0.f;
        #pragma unroll
        for (int j = 0; j < 25; j++) {
            const float4 f = f4[j];
            const float4 g = g4[j];
            a0 = fmaf(f.x, g.x, a0);
            a1 = fmaf(f.y, g.y, a1);
            a2 = fmaf(f.z, g.z, a2);
            a3 = fmaf(f.w, g.w, a3);
        }
        const float hv = (a0 + a1) + (a2 + a3) + b1s[o];
        const float sw = hv * fast_sigmoid(hv);
        h1n[i * 60 + o] = 2.0f * sw - 1.0f;
    }
    __syncthreads();

    const int i   = lane & 15;
    const int sub = lane >> 4;

    // ======== Phase 3: h2 = swish(h1n @ w2.T + b2), 16x16 ===================
    {
        const int o = 2 * wid + sub;                 // 0..15
        const float4* f4 = (const float4*)&h1n[i * 60];
        const float4* g4 = (const float4*)&w2s[o * 60];
        float a0 = 0.f, a1 = 0.f, a2 = 0.f, a3 = 0.f;
        #pragma unroll
        for (int j = 0; j < 15; j++) {
            const float4 f = f4[j];
            const float4 g = g4[j];
            a0 = fmaf(f.x, g.x, a0);
            a1 = fmaf(f.y, g.y, a1);
            a2 = fmaf(f.z, g.z, a2);
            a3 = fmaf(f.w, g.w, a3);
        }
        const float hv = (a0 + a1) + (a2 + a3) + b2s[o];
        h2s[i * 16 + o] = hv * fast_sigmoid(hv);
    }
    __syncthreads();

    // ======== Phase 4: y = h2 @ w3.T + b3 (128 outputs) =====================
    if (tid < 128) {
        const int ii = tid >> 3;
        const int o  = tid & 7;
        const float4* f4 = (const float4*)&h2s[ii * 16];
        const float4* g4 = (const float4*)&w3s[o * 16];
        float acc = 0.f;
        #pragma unroll
        for (int j = 0; j < 4; j++) {
            const float4 f = f4[j];
            const float4 g = g4[j];
            acc = fmaf(f.x, g.x, acc);
            acc = fmaf(f.y, g.y, acc);
            acc = fmaf(f.z, g.z, acc);
            acc = fmaf(f.w, g.w, acc);
        }
        out[tid] = acc + b3s[o];
    }
}

extern "C" void kernel_launch(void* const* d_in, const int* in_sizes, int n_in,
                              void* d_out, int out_size)
{
    const float* x        = (const float*)d_in[0];
    const float* conv_w   = (const float*)d_in[1];
    const float* conv_b   = (const float*)d_in[2];
    const float* bn_gamma = (const float*)d_in[3];
    const float* bn_beta  = (const float*)d_in[4];
    const float* bn_mean  = (const float*)d_in[5];
    const float* bn_var   = (const float*)d_in[6];
    const float* w1       = (const float*)d_in[7];
    const float* b1       = (const float*)d_in[8];
    const float* w2       = (const float*)d_in[9];
    const float* b2       = (const float*)d_in[10];
    const float* w3       = (const float*)d_in[11];
    const float* b3       = (const float*)d_in[12];
    float* out = (float*)d_out;

    model_fused_kernel<<<1, 256>>>(x, conv_w, conv_b, bn_gamma, bn_beta,
                                   bn_mean, bn_var, w1, b1, w2, b2, w3, b3, out);
}